// round 1
// baseline (speedup 1.0000x reference)
#include <cuda_runtime.h>
#include <math.h>
#include <stdint.h>

#define NN 10000
#define NE 160000
#define HASH_BITS 19
#define HASH_SIZE (1<<HASH_BITS)
#define HASH_MASK (HASH_SIZE-1)

// ---------------- device scratch (no runtime allocation allowed) ----------------
__device__ float g_cat[(size_t)NE*512];     // edge-MLP input  [E,512]
__device__ float g_hid[(size_t)NE*384];     // edge-MLP hidden [E,384]
__device__ float g_ek [(size_t)NE*128];     // k = ef@kW per edge
__device__ float g_upd[(size_t)NE*128];     // upd_edge (layer 0)
__device__ float g_ef [(size_t)NE*128];     // ef between layers
__device__ float g_x  [NN*128];             // x between layers
__device__ float g_nq [NN*128];             // x@qW+qB per node
__device__ float g_nv [NN*128];             // x@vW+vB per node
__device__ unsigned g_agg[NN*128];          // segment-max accumulator (encoded)
__device__ float g_outf[NN*128];
__device__ float g_incf[NN*128];
__device__ float g_ncat[NN*256];
__device__ float g_nhid[NN*256];
__device__ float g_und [NN*128];            // upd_node
__device__ float g_acat[NN*256];
__device__ float g_eatt[NN*128];
__device__ int   g_rev [NE];
__device__ int   g_hkey[HASH_SIZE];
__device__ int   g_hval[HASH_SIZE];
__device__ int   g_cout[NN];
__device__ int   g_cin [NN];

// encoded -inf: enc(f) = f>=0 ? bits|0x80000000 : ~bits ; enc(-inf) = ~0xFF800000
#define NEGINF_ENC 0x007FFFFFu

// ---------------- precompute kernels ----------------
__global__ void k_pre_init(int n) {
    int i = blockIdx.x * 256 + threadIdx.x;
    if (i < HASH_SIZE) { g_hkey[i] = -1; g_hval[i] = 0x7FFFFFFF; }
    if (i < n) { g_cout[i] = 0; g_cin[i] = 0; }
}

__global__ void k_hash_insert(const int* __restrict__ row, const int* __restrict__ col,
                              int E, int N) {
    int e = blockIdx.x * 256 + threadIdx.x;
    if (e >= E) return;
    int r = row[e], c = col[e];
    atomicAdd(&g_cout[r], 1);
    atomicAdd(&g_cin[c], 1);
    int key = r * N + c;                       // < 1e8, fits int32
    unsigned slot = ((unsigned)key * 2654435761u) & HASH_MASK;
    while (true) {
        int old = atomicCAS(&g_hkey[slot], -1, key);
        if (old == -1 || old == key) { atomicMin(&g_hval[slot], e); break; }
        slot = (slot + 1) & HASH_MASK;
    }
}

__global__ void k_rev_lookup(const int* __restrict__ row, const int* __restrict__ col,
                             int E, int N) {
    int e = blockIdx.x * 256 + threadIdx.x;
    if (e >= E) return;
    int rkey = col[e] * N + row[e];
    unsigned slot = ((unsigned)rkey * 2654435761u) & HASH_MASK;
    int rv = -1;
    while (true) {
        int k = g_hkey[slot];
        if (k == rkey) { rv = g_hval[slot]; break; }
        if (k == -1) break;
        slot = (slot + 1) & HASH_MASK;
    }
    g_rev[e] = rv;
}

// ---------------- per-layer init ----------------
__global__ void k_layer_init(int n128) {
    int i = blockIdx.x * 256 + threadIdx.x;
    if (i >= n128) return;
    g_outf[i] = 0.f; g_incf[i] = 0.f; g_agg[i] = NEGINF_ENC;
}

// ---------------- generic SGEMM: C = epi(A[MxK] @ B[KxN] + bias) ----------------
// BM=BN=128, BK=8, 256 threads, 8x8 per thread. N must be a multiple of 128,
// K a multiple of 8 (true for all call sites). M guarded.
template<int EPI>
__launch_bounds__(256)
__global__ void sgemm(const float* __restrict__ A, const float* __restrict__ B,
                      const float* __restrict__ bias, float* __restrict__ C,
                      int M, int N, int K) {
    __shared__ float As[8][128];
    __shared__ float Bs[8][128];
    int tid = threadIdx.x;
    int bm = blockIdx.y * 128, bn = blockIdx.x * 128;
    int aRow = tid >> 1, aCol = (tid & 1) * 4;
    int bRow = tid >> 5, bCol = (tid & 31) * 4;
    int ty = tid >> 4, tx = tid & 15;
    float acc[8][8];
#pragma unroll
    for (int i = 0; i < 8; i++)
#pragma unroll
        for (int j = 0; j < 8; j++) acc[i][j] = 0.f;

    for (int k0 = 0; k0 < K; k0 += 8) {
        float4 av = make_float4(0.f, 0.f, 0.f, 0.f);
        if (bm + aRow < M)
            av = *(const float4*)(A + (long)(bm + aRow) * K + k0 + aCol);
        As[aCol + 0][aRow] = av.x;
        As[aCol + 1][aRow] = av.y;
        As[aCol + 2][aRow] = av.z;
        As[aCol + 3][aRow] = av.w;
        float4 bv = *(const float4*)(B + (long)(k0 + bRow) * N + bn + bCol);
        *(float4*)&Bs[bRow][bCol] = bv;
        __syncthreads();
#pragma unroll
        for (int kk = 0; kk < 8; kk++) {
            float a[8], b[8];
#pragma unroll
            for (int i = 0; i < 8; i++) a[i] = As[kk][ty * 8 + i];
#pragma unroll
            for (int j = 0; j < 8; j++) b[j] = Bs[kk][tx * 8 + j];
#pragma unroll
            for (int i = 0; i < 8; i++)
#pragma unroll
                for (int j = 0; j < 8; j++) acc[i][j] += a[i] * b[j];
        }
        __syncthreads();
    }
#pragma unroll
    for (int i = 0; i < 8; i++) {
        int r = bm + ty * 8 + i;
        if (r >= M) continue;
#pragma unroll
        for (int jj = 0; jj < 2; jj++) {
            int c = bn + tx * 8 + jj * 4;
            float4 v;
            float t0 = acc[i][jj*4+0] + bias[c+0];
            float t1 = acc[i][jj*4+1] + bias[c+1];
            float t2 = acc[i][jj*4+2] + bias[c+2];
            float t3 = acc[i][jj*4+3] + bias[c+3];
            if (EPI == 1) { t0=fmaxf(t0,0.f); t1=fmaxf(t1,0.f); t2=fmaxf(t2,0.f); t3=fmaxf(t3,0.f); }
            if (EPI == 2) {
                t0 = 1.f/(1.f+expf(-t0)); t1 = 1.f/(1.f+expf(-t1));
                t2 = 1.f/(1.f+expf(-t2)); t3 = 1.f/(1.f+expf(-t3));
            }
            v.x=t0; v.y=t1; v.z=t2; v.w=t3;
            *(float4*)(C + (long)r * N + c) = v;
        }
    }
}

// ---------------- build edge-MLP input [x_i | ef | rev | x_j] ----------------
__global__ void k_cat(const float* __restrict__ x, const float* __restrict__ ef,
                      const int* __restrict__ row, const int* __restrict__ col, int E) {
    int idx = blockIdx.x * 256 + threadIdx.x;   // one float4 per thread over E*128
    if (idx >= E * 128) return;
    int e = idx >> 7, q = idx & 127;
    int seg = q >> 5, o = (q & 31) * 4;
    float4 v;
    if (seg == 0)       v = *(const float4*)(x + (long)row[e] * 128 + o);
    else if (seg == 1)  v = *(const float4*)(ef + (long)e * 128 + o);
    else if (seg == 2) {
        int rv = g_rev[e];
        v = (rv >= 0) ? *(const float4*)(ef + (long)rv * 128 + o)
                      : make_float4(0.f, 0.f, 0.f, 0.f);
    } else              v = *(const float4*)(x + (long)col[e] * 128 + o);
    *(float4*)(g_cat + (long)e * 512 + seg * 128 + o) = v;
}

// ---------------- attention + softmax + wv + segment_max + prob output ----------------
// one thread per (edge, head)
__launch_bounds__(256)
__global__ void k_attn(const float* __restrict__ desc,
                       const int* __restrict__ row, const int* __restrict__ col,
                       const float* __restrict__ W1, const float* __restrict__ B1,
                       const float* __restrict__ W2, const float* __restrict__ B2,
                       const float* __restrict__ dW1, const float* __restrict__ dB1,
                       const float* __restrict__ dW2, const float* __restrict__ dB2,
                       float* __restrict__ probout, int E) {
    __shared__ float sW1[1024], sW2[512], sB1[32], sB2[16];
    __shared__ float sdW1[128], sdB1[32], sdW2[32], sdB2;
    int tid = threadIdx.x;
    for (int i = tid; i < 1024; i += 256) sW1[i] = W1[i];
    for (int i = tid; i < 512;  i += 256) sW2[i] = W2[i];
    if (tid < 32) { sB1[tid] = B1[tid]; sdB1[tid] = dB1[tid]; sdW2[tid] = dW2[tid]; }
    if (tid < 16) sB2[tid] = B2[tid];
    if (tid >= 32 && tid < 160) sdW1[tid - 32] = dW1[tid - 32];
    if (tid == 0) sdB2 = dB2[0];
    __syncthreads();

    int gid = blockIdx.x * 256 + tid;
    if (gid >= E * 8) return;
    int e = gid >> 3, h = gid & 7;
    int r = row[e], c = col[e];

    float hv[32];
#pragma unroll
    for (int i = 0; i < 16; i++) hv[i]      = g_nq[r * 128 + i * 8 + h];
#pragma unroll
    for (int i = 0; i < 16; i++) hv[16 + i] = g_ek[(long)e * 128 + i * 8 + h];

    float h1[32];
#pragma unroll
    for (int o = 0; o < 32; o++) {
        float s = sB1[o];
#pragma unroll
        for (int cc = 0; cc < 32; cc++) s += sW1[o * 32 + cc] * hv[cc];
        h1[o] = fmaxf(s, 0.f);
    }
    float att[16];
#pragma unroll
    for (int o = 0; o < 16; o++) {
        float s = sB2[o];
#pragma unroll
        for (int cc = 0; cc < 32; cc++) s += sW2[o * 32 + cc] * h1[cc];
        att[o] = s;
    }
    // distance gate dm
    float dx = desc[r * 8 + 0] - desc[c * 8 + 0];
    float dy = desc[r * 8 + 1] - desc[c * 8 + 1];
    float dz = desc[r * 8 + 2] - desc[c * 8 + 2];
    float dist = sqrtf(dx * dx + dy * dy + dz * dz);
    float f4[4] = {dx, dy, dz, dist};
    float s2 = sdB2;
#pragma unroll
    for (int j = 0; j < 32; j++) {
        float z = sdB1[j];
#pragma unroll
        for (int i = 0; i < 4; i++) z += f4[i] * sdW1[i * 32 + j];
        s2 += fmaxf(z, 0.f) * sdW2[j];
    }
    float dm = 1.f / (1.f + expf(-s2));

    float m = -1e30f;
#pragma unroll
    for (int o = 0; o < 16; o++) { att[o] = att[o] * dm * 0.25f; m = fmaxf(m, att[o]); }
    float sum = 0.f;
#pragma unroll
    for (int o = 0; o < 16; o++) { att[o] = expf(att[o] - m); sum += att[o]; }
    float inv = 1.f / sum;
#pragma unroll
    for (int o = 0; o < 16; o++) {
        float p = att[o] * inv;
        probout[(long)e * 128 + o * 8 + h] = p;
        float wv = p * g_nv[c * 128 + o * 8 + h];
        unsigned u = __float_as_uint(wv);
        u = (u & 0x80000000u) ? ~u : (u | 0x80000000u);
        atomicMax(&g_agg[r * 128 + o * 8 + h], u);
    }
}

// ---------------- segment sums of upd_edge ----------------
__global__ void k_scatter(const float* __restrict__ ue,
                          const int* __restrict__ row, const int* __restrict__ col, int E) {
    int idx = blockIdx.x * 256 + threadIdx.x;
    if (idx >= E * 128) return;
    int e = idx >> 7, cc = idx & 127;
    float v = ue[idx];
    atomicAdd(&g_outf[row[e] * 128 + cc], v);
    atomicAdd(&g_incf[col[e] * 128 + cc], v);
}

// ---------------- node-side small kernels ----------------
__global__ void k_ncat(const float* __restrict__ x, int n) {
    int idx = blockIdx.x * 256 + threadIdx.x;
    if (idx >= n * 256) return;
    int nd = idx >> 8, cc = idx & 255;
    float v;
    if (cc < 128) v = x[nd * 128 + cc];
    else {
        unsigned u = g_agg[nd * 128 + cc - 128];
        float f = (u & 0x80000000u) ? __uint_as_float(u ^ 0x80000000u)
                                    : __uint_as_float(~u);
        v = (u == NEGINF_ENC) ? 0.f : f;
    }
    g_ncat[idx] = v;
}

__global__ void k_acat(int n) {
    int idx = blockIdx.x * 256 + threadIdx.x;
    if (idx >= n * 256) return;
    int nd = idx >> 8, cc = idx & 255;
    float v;
    if (cc < 128) v = g_outf[nd * 128 + cc] / fmaxf((float)g_cout[nd], 1.f);
    else          v = g_incf[nd * 128 + cc - 128] / fmaxf((float)g_cin[nd], 1.f);
    g_acat[idx] = v;
}

__global__ void k_final(float* __restrict__ dst, int n) {
    int idx = blockIdx.x * 256 + threadIdx.x;
    if (idx >= n * 128) return;
    dst[idx] = fmaxf(g_und[idx], 0.f) * g_eatt[idx];
}

__global__ void k_efrelu(int E) {
    int idx = blockIdx.x * 256 + threadIdx.x;
    if (idx >= E * 128) return;
    g_ef[idx] = fmaxf(g_upd[idx], 0.f);
}

// ---------------- host side ----------------
static void* symaddr(const void* s) { void* p = nullptr; cudaGetSymbolAddress(&p, s); return p; }

static void gemm(int epi, const float* A, const float* B, const float* bias,
                 float* C, int M, int N, int K) {
    dim3 g(N / 128, (M + 127) / 128);
    if (epi == 0)      sgemm<0><<<g, 256>>>(A, B, bias, C, M, N, K);
    else if (epi == 1) sgemm<1><<<g, 256>>>(A, B, bias, C, M, N, K);
    else               sgemm<2><<<g, 256>>>(A, B, bias, C, M, N, K);
}

extern "C" void kernel_launch(void* const* d_in, const int* in_sizes, int n_in,
                              void* d_out, int out_size) {
    const float* x0   = (const float*)d_in[0];
    const float* ef0  = (const float*)d_in[1];
    const int*   eidx = (const int*)d_in[2];
    const float* desc = (const float*)d_in[3];
    const float* qW   = (const float*)d_in[4];
    const float* qB   = (const float*)d_in[5];
    const float* kW   = (const float*)d_in[6];
    const float* kB   = (const float*)d_in[7];
    const float* vW   = (const float*)d_in[8];
    const float* vB   = (const float*)d_in[9];
    const float* dW1  = (const float*)d_in[10];
    const float* dB1  = (const float*)d_in[11];
    const float* dW2  = (const float*)d_in[12];
    const float* dB2  = (const float*)d_in[13];
    const float* eW1  = (const float*)d_in[14];
    const float* eB1  = (const float*)d_in[15];
    const float* eW2  = (const float*)d_in[16];
    const float* eB2  = (const float*)d_in[17];
    const float* aW1  = (const float*)d_in[18];
    const float* aB1  = (const float*)d_in[19];
    const float* aW2  = (const float*)d_in[20];
    const float* aB2  = (const float*)d_in[21];
    const float* nW1  = (const float*)d_in[22];
    const float* nB1  = (const float*)d_in[23];
    const float* nW2  = (const float*)d_in[24];
    const float* nB2  = (const float*)d_in[25];
    const float* aW   = (const float*)d_in[26];
    const float* aB   = (const float*)d_in[27];

    int N = in_sizes[0] / 128;   // 10000
    int E = in_sizes[1] / 128;   // 160000
    const int* row = eidx;
    const int* col = eidx + E;

    float* out      = (float*)d_out;
    float* out_x    = out;
    float* out_ef   = out + (size_t)N * 128;
    float* out_prob = out_ef + (size_t)E * 128;

    float* p_cat  = (float*)symaddr(g_cat);
    float* p_hid  = (float*)symaddr(g_hid);
    float* p_ek   = (float*)symaddr(g_ek);
    float* p_upd  = (float*)symaddr(g_upd);
    float* p_ef   = (float*)symaddr(g_ef);
    float* p_x    = (float*)symaddr(g_x);
    float* p_nq   = (float*)symaddr(g_nq);
    float* p_nv   = (float*)symaddr(g_nv);
    float* p_ncat = (float*)symaddr(g_ncat);
    float* p_nhid = (float*)symaddr(g_nhid);
    float* p_und  = (float*)symaddr(g_und);
    float* p_acat = (float*)symaddr(g_acat);
    float* p_eatt = (float*)symaddr(g_eatt);

    // -------- precompute (reverse-edge map, degrees) --------
    k_pre_init<<<(HASH_SIZE + 255) / 256, 256>>>(N);
    k_hash_insert<<<(E + 255) / 256, 256>>>(row, col, E, N);
    k_rev_lookup<<<(E + 255) / 256, 256>>>(row, col, E, N);

    const int L = 2;
    for (int l = 0; l < L; l++) {
        const float* xc  = (l == 0) ? x0  : p_x;
        const float* efc = (l == 0) ? ef0 : p_ef;
        float* upd_t = (l == L - 1) ? out_ef : p_upd;

        // per-layer weight slices
        const float* qW_l  = qW  + (size_t)l * 128 * 128;
        const float* qB_l  = qB  + (size_t)l * 128;
        const float* kW_l  = kW  + (size_t)l * 128 * 128;
        const float* kB_l  = kB  + (size_t)l * 128;
        const float* vW_l  = vW  + (size_t)l * 128 * 128;
        const float* vB_l  = vB  + (size_t)l * 128;
        const float* dW1_l = dW1 + (size_t)l * 4 * 32;
        const float* dB1_l = dB1 + (size_t)l * 32;
        const float* dW2_l = dW2 + (size_t)l * 32;
        const float* dB2_l = dB2 + (size_t)l * 1;
        const float* eW1_l = eW1 + (size_t)l * 512 * 384;
        const float* eB1_l = eB1 + (size_t)l * 384;
        const float* eW2_l = eW2 + (size_t)l * 384 * 128;
        const float* eB2_l = eB2 + (size_t)l * 128;
        const float* aW1_l = aW1 + (size_t)l * 32 * 32;
        const float* aB1_l = aB1 + (size_t)l * 32;
        const float* aW2_l = aW2 + (size_t)l * 16 * 32;
        const float* aB2_l = aB2 + (size_t)l * 16;
        const float* nW1_l = nW1 + (size_t)l * 256 * 256;
        const float* nB1_l = nB1 + (size_t)l * 256;
        const float* nW2_l = nW2 + (size_t)l * 256 * 128;
        const float* nB2_l = nB2 + (size_t)l * 128;
        const float* aW_l  = aW  + (size_t)l * 256 * 128;
        const float* aB_l  = aB  + (size_t)l * 128;

        k_layer_init<<<(N * 128 + 255) / 256, 256>>>(N * 128);

        // node-level q, v ; edge-level k
        gemm(0, xc,  qW_l, qB_l, p_nq, N, 128, 128);
        gemm(0, xc,  vW_l, vB_l, p_nv, N, 128, 128);
        gemm(0, efc, kW_l, kB_l, p_ek, E, 128, 128);

        // edge MLP (the big one)
        k_cat<<<(E * 128 + 255) / 256, 256>>>(xc, efc, row, col, E);
        gemm(1, p_cat, eW1_l, eB1_l, p_hid, E, 384, 512);
        gemm(0, p_hid, eW2_l, eB2_l, upd_t, E, 128, 384);

        // attention -> prob out + segment_max(wv)
        k_attn<<<(E * 8 + 255) / 256, 256>>>(desc, row, col,
                                             aW1_l, aB1_l, aW2_l, aB2_l,
                                             dW1_l, dB1_l, dW2_l, dB2_l,
                                             out_prob + (size_t)l * E * 128, E);

        // segment sums of upd_edge
        k_scatter<<<(E * 128 + 255) / 256, 256>>>(upd_t, row, col, E);

        // node MLP
        k_ncat<<<(N * 256 + 255) / 256, 256>>>(xc, N);
        gemm(1, p_ncat, nW1_l, nB1_l, p_nhid, N, 256, 256);
        gemm(0, p_nhid, nW2_l, nB2_l, p_und,  N, 128, 256);

        // edge-attention gate
        k_acat<<<(N * 256 + 255) / 256, 256>>>(N);
        gemm(2, p_acat, aW_l, aB_l, p_eatt, N, 128, 256);

        // final node features (>=0, so inter-layer relu is a no-op)
        float* xdst = (l == L - 1) ? out_x : p_x;
        k_final<<<(N * 128 + 255) / 256, 256>>>(xdst, N);

        // inter-layer edge relu
        if (l < L - 1)
            k_efrelu<<<(E * 128 + 255) / 256, 256>>>(E);
    }
}